// round 5
// baseline (speedup 1.0000x reference)
#include <cuda_runtime.h>
#include <cstdint>

// Problem constants
#define NB 2
#define NS 2048
#define ND 1024
#define NH 16
#define NDH 64
#define NM (NB * NS)

// Scratch (device globals: allocation-free)
__device__ float g_q[(size_t)NB * NH * NS * NDH];
__device__ float g_k[(size_t)NB * NH * NS * NDH];
__device__ float g_v[(size_t)NB * NH * NS * NDH];
__device__ float g_attn[(size_t)NB * NS * ND];
__device__ float g_rowsum[(size_t)NB * NH * NS];

// ---------------- tf32 mma helpers ----------------
__device__ __forceinline__ uint32_t f2tf(float f) {
    uint32_t u;
    asm("cvt.rna.tf32.f32 %0, %1;" : "=r"(u) : "f"(f));
    return u;
}
__device__ __forceinline__ float uaf(uint32_t u) { return __uint_as_float(u); }
__device__ __forceinline__ uint32_t fau(float f) { return __float_as_uint(f); }

__device__ __forceinline__ void mma_tf32(float c[4], const uint32_t a[4], const uint32_t b[2]) {
    asm volatile(
        "mma.sync.aligned.m16n8k8.row.col.f32.tf32.tf32.f32 "
        "{%0,%1,%2,%3}, {%4,%5,%6,%7}, {%8,%9}, {%0,%1,%2,%3};"
        : "+f"(c[0]), "+f"(c[1]), "+f"(c[2]), "+f"(c[3])
        : "r"(a[0]), "r"(a[1]), "r"(a[2]), "r"(a[3]), "r"(b[0]), "r"(b[1]));
}

// ---------------------------------------------------------------------------
// GEMM (round-2 known-good version): C = A @ W^T + bias, tf32, single-buffer.
// M=4096, N=K=1024. BM=BN=128, BK=16, 256 threads, warp tile 32x64.
// SPLIT=1: out (b,h,s,dh); SPLIT=0: row-major (m,n).
// ---------------------------------------------------------------------------
#define GS 20
template <int SPLIT>
__global__ __launch_bounds__(256) void gemm_tf32(
    const float* __restrict__ A, const float* __restrict__ W,
    const float* __restrict__ bias, float* __restrict__ out)
{
    __shared__ float As[128 * GS];
    __shared__ float Ws[128 * GS];

    const int tid = threadIdx.x;
    const int wid = tid >> 5, lane = tid & 31;
    const int g = lane >> 2, t = lane & 3;
    const int wm = (wid & 3) * 32;
    const int wn = (wid >> 2) * 64;
    const int bm = blockIdx.y * 128, bn = blockIdx.x * 128;

    const int lr = tid >> 1;
    const int lk = (tid & 1) * 8;

    float c[2][8][4];
#pragma unroll
    for (int i = 0; i < 2; i++)
#pragma unroll
        for (int j = 0; j < 8; j++)
#pragma unroll
            for (int q = 0; q < 4; q++) c[i][j][q] = 0.f;

    const float* aptr = A + (size_t)(bm + lr) * ND + lk;
    const float* wptr = W + (size_t)(bn + lr) * ND + lk;

    for (int k0 = 0; k0 < ND; k0 += 16) {
        float4 a0 = *(const float4*)(aptr + k0);
        float4 a1 = *(const float4*)(aptr + k0 + 4);
        float4 w0 = *(const float4*)(wptr + k0);
        float4 w1 = *(const float4*)(wptr + k0 + 4);
        __syncthreads();
        *(float4*)&As[lr * GS + lk]     = make_float4(uaf(f2tf(a0.x)), uaf(f2tf(a0.y)), uaf(f2tf(a0.z)), uaf(f2tf(a0.w)));
        *(float4*)&As[lr * GS + lk + 4] = make_float4(uaf(f2tf(a1.x)), uaf(f2tf(a1.y)), uaf(f2tf(a1.z)), uaf(f2tf(a1.w)));
        *(float4*)&Ws[lr * GS + lk]     = make_float4(uaf(f2tf(w0.x)), uaf(f2tf(w0.y)), uaf(f2tf(w0.z)), uaf(f2tf(w0.w)));
        *(float4*)&Ws[lr * GS + lk + 4] = make_float4(uaf(f2tf(w1.x)), uaf(f2tf(w1.y)), uaf(f2tf(w1.z)), uaf(f2tf(w1.w)));
        __syncthreads();

#pragma unroll
        for (int kk = 0; kk < 16; kk += 8) {
            uint32_t af[2][4];
#pragma unroll
            for (int mt = 0; mt < 2; mt++) {
                const int r = wm + mt * 16;
                af[mt][0] = fau(As[(r + g)     * GS + kk + t]);
                af[mt][1] = fau(As[(r + g + 8) * GS + kk + t]);
                af[mt][2] = fau(As[(r + g)     * GS + kk + t + 4]);
                af[mt][3] = fau(As[(r + g + 8) * GS + kk + t + 4]);
            }
#pragma unroll
            for (int nt = 0; nt < 8; nt++) {
                uint32_t bf[2];
                const int col = wn + nt * 8;
                bf[0] = fau(Ws[(col + g) * GS + kk + t]);
                bf[1] = fau(Ws[(col + g) * GS + kk + t + 4]);
                mma_tf32(c[0][nt], af[0], bf);
                mma_tf32(c[1][nt], af[1], bf);
            }
        }
    }

#pragma unroll
    for (int mt = 0; mt < 2; mt++) {
#pragma unroll
        for (int rr = 0; rr < 2; rr++) {
            const int m = bm + wm + mt * 16 + g + rr * 8;
            const int b = m >> 11, sIdx = m & (NS - 1);
#pragma unroll
            for (int nt = 0; nt < 8; nt++) {
                const int col = bn + wn + nt * 8 + 2 * t;
                float2 v;
                v.x = c[mt][nt][rr * 2 + 0] + bias[col];
                v.y = c[mt][nt][rr * 2 + 1] + bias[col + 1];
                if (SPLIT) {
                    const int h = col >> 6, dh = col & 63;
                    *(float2*)&out[((size_t)(b * NH + h) * NS + sIdx) * NDH + dh] = v;
                } else {
                    *(float2*)&out[(size_t)m * ND + col] = v;
                }
            }
        }
    }
}

// ---------------------------------------------------------------------------
// Attention v5: 256 threads (8 warps), 128 q rows per block.
// Warp = 16 q rows x FULL 64 keys; S-MMA output fragment reused directly as
// PV A-fragment via key-permuted V layout (validated rounds 3-4):
//   e never touches smem; no sync between S and PV phases.
// 8 warps share each 64-key K/V staging (2x better amortization than v4).
// Smem: Ks 64x68 + Vs 64x72 = 35,840 B (Q staged into the union first).
// ---------------------------------------------------------------------------
__global__ __launch_bounds__(256) void attn_tf32(
    const int* __restrict__ mask, float* __restrict__ wout)
{
    __shared__ float Ks[64 * 68];
    __shared__ float Vs[64 * 72];

    const int b = blockIdx.z, h = blockIdx.y;
    const int q0 = blockIdx.x * 128;
    const int tid = threadIdx.x;
    const int wid = tid >> 5, lane = tid & 31;
    const int g = lane >> 2, t = lane & 3;
    const int wq = wid * 16;                 // warp's q-row base within block
    const size_t bh = (size_t)(b * NH + h);

    const int qr0 = q0 + wq + g;             // global q rows owned by thread
    const int qr1 = qr0 + 8;

    // Stage Q (128x64, tf32) into the Ks|Vs union (stride 68 both halves)
    const float* qptr = g_q + (bh * NS + q0) * NDH;
#pragma unroll
    for (int i = 0; i < 8; i++) {
        const int lin = tid + i * 256;
        const int r = lin >> 4, c4 = (lin & 15) * 4;
        float* dst = (r < 64) ? &Ks[r * 68 + c4] : &Vs[(r - 64) * 68 + c4];
        float4 v = *(const float4*)(qptr + r * NDH + c4);
        *(float4*)dst = make_float4(uaf(f2tf(v.x)), uaf(f2tf(v.y)), uaf(f2tf(v.z)), uaf(f2tf(v.w)));
    }
    __syncthreads();

    // Q fragments: 8 k-chunks x 4 regs = 32 registers, resident all kernel
    const int row0 = wq + g, row1 = wq + g + 8;   // both in [wq, wq+16)
    const float* q0p = (row0 < 64) ? &Ks[row0 * 68] : &Vs[(row0 - 64) * 68];
    const float* q1p = (row1 < 64) ? &Ks[row1 * 68] : &Vs[(row1 - 64) * 68];
    uint32_t qf[8][4];
#pragma unroll
    for (int kd = 0; kd < 8; kd++) {
        qf[kd][0] = fau(q0p[kd * 8 + t]);
        qf[kd][1] = fau(q1p[kd * 8 + t]);
        qf[kd][2] = fau(q0p[kd * 8 + t + 4]);
        qf[kd][3] = fau(q1p[kd * 8 + t + 4]);
    }

    float cacc[8][4];
#pragma unroll
    for (int nd = 0; nd < 8; nd++)
#pragma unroll
        for (int q = 0; q < 4; q++) cacc[nd][q] = 0.f;
    float rs0 = 0.f, rs1 = 0.f;

    const int* mbase = mask + (size_t)b * NS * NS;
    float* wbase = wout ? wout + bh * NS * NS : nullptr;

    for (int kt = 0; kt < NS / 64; kt++) {
        __syncthreads();   // prev tile reads done (covers qf build on kt=0)
        const float* kptr = g_k + (bh * NS + kt * 64) * NDH;
        const float* vptr = g_v + (bh * NS + kt * 64) * NDH;
#pragma unroll
        for (int i = 0; i < 4; i++) {
            const int lin = tid + i * 256;
            const int r = lin >> 4, c4 = (lin & 15) * 4;
            float4 kv = *(const float4*)(kptr + r * NDH + c4);
            float4 vv = *(const float4*)(vptr + r * NDH + c4);
            *(float4*)&Ks[r * 68 + c4] =
                make_float4(uaf(f2tf(kv.x)), uaf(f2tf(kv.y)), uaf(f2tf(kv.z)), uaf(f2tf(kv.w)));
            // V staged with per-8-group key permutation sigma(c) = 4*(c&1) + (c>>1)
            const int slot = (r & ~7) | (4 * (r & 1) + ((r & 7) >> 1));
            *(float4*)&Vs[slot * 72 + c4] =
                make_float4(uaf(f2tf(vv.x)), uaf(f2tf(vv.y)), uaf(f2tf(vv.z)), uaf(f2tf(vv.w)));
        }
        __syncthreads();

        // Per 8-key chunk: S-MMAs -> mask/exp -> weights STG -> PV-MMAs
#pragma unroll
        for (int kc = 0; kc < 8; kc++) {
            float lg[4] = {0.f, 0.f, 0.f, 0.f};
#pragma unroll
            for (int kd = 0; kd < 8; kd++) {
                uint32_t bf[2];
                bf[0] = fau(Ks[(kc * 8 + g) * 68 + kd * 8 + t]);
                bf[1] = fau(Ks[(kc * 8 + g) * 68 + kd * 8 + t + 4]);
                mma_tf32(lg, qf[kd], bf);
            }
            const int col = kt * 64 + kc * 8 + 2 * t;
            int2 m0 = *(const int2*)(mbase + (size_t)qr0 * NS + col);
            int2 m1 = *(const int2*)(mbase + (size_t)qr1 * NS + col);
            float e0 = m0.x ? 0.f : __expf(lg[0] * 0.125f);
            float e1 = m0.y ? 0.f : __expf(lg[1] * 0.125f);
            float e2 = m1.x ? 0.f : __expf(lg[2] * 0.125f);
            float e3 = m1.y ? 0.f : __expf(lg[3] * 0.125f);
            rs0 += e0 + e1;
            rs1 += e2 + e3;
            if (wbase) {
                *(float2*)&wbase[(size_t)qr0 * NS + col] = make_float2(e0, e1);
                *(float2*)&wbase[(size_t)qr1 * NS + col] = make_float2(e2, e3);
            }
            // A-frag for PV over permuted key slots: (e0, e2, e1, e3)
            uint32_t af[4] = { f2tf(e0), f2tf(e2), f2tf(e1), f2tf(e3) };
#pragma unroll
            for (int nd = 0; nd < 8; nd++) {
                uint32_t bf[2];
                bf[0] = fau(Vs[(kc * 8 + t)     * 72 + nd * 8 + g]);
                bf[1] = fau(Vs[(kc * 8 + t + 4) * 72 + nd * 8 + g]);
                mma_tf32(cacc[nd], af, bf);
            }
        }
    }

    // Rowsums: warp owns full rows; reduce over t within each quad
    rs0 += __shfl_xor_sync(0xffffffffu, rs0, 1);
    rs0 += __shfl_xor_sync(0xffffffffu, rs0, 2);
    rs1 += __shfl_xor_sync(0xffffffffu, rs1, 1);
    rs1 += __shfl_xor_sync(0xffffffffu, rs1, 2);
    if (t == 0) {
        g_rowsum[bh * NS + qr0] = rs0;
        g_rowsum[bh * NS + qr1] = rs1;
    }
    const float inv0 = 1.f / rs0, inv1 = 1.f / rs1;

    // Normalized attn, concat layout (b, s, h*64 + dh)
#pragma unroll
    for (int nd = 0; nd < 8; nd++) {
        const int dh = nd * 8 + 2 * t;
        *(float2*)&g_attn[((size_t)b * NS + qr0) * ND + h * NDH + dh] =
            make_float2(cacc[nd][0] * inv0, cacc[nd][1] * inv0);
        *(float2*)&g_attn[((size_t)b * NS + qr1) * ND + h * NDH + dh] =
            make_float2(cacc[nd][2] * inv1, cacc[nd][3] * inv1);
    }
}

// Scale each weights row by 1/rowsum
__global__ __launch_bounds__(128) void norm_w(float* __restrict__ w)
{
    const int row = blockIdx.x;
    const float inv = 1.f / g_rowsum[row];
    float4* p = (float4*)(w + (size_t)row * NS);
#pragma unroll
    for (int i = threadIdx.x; i < NS / 4; i += 128) {
        float4 v = p[i];
        v.x *= inv; v.y *= inv; v.z *= inv; v.w *= inv;
        p[i] = v;
    }
}

extern "C" void kernel_launch(void* const* d_in, const int* in_sizes, int n_in,
                              void* d_out, int out_size)
{
    const float* Xq  = (const float*)d_in[0];
    const float* Xk  = (const float*)d_in[1];
    const float* Xv  = (const float*)d_in[2];
    const int*   msk = (const int*)d_in[3];
    const float* Wq  = (const float*)d_in[4];
    const float* bq  = (const float*)d_in[5];
    const float* Wk  = (const float*)d_in[6];
    const float* bk  = (const float*)d_in[7];
    const float* Wv  = (const float*)d_in[8];
    const float* bv  = (const float*)d_in[9];
    const float* Wo  = (const float*)d_in[10];
    const float* bo  = (const float*)d_in[11];

    float* out = (float*)d_out;
    const size_t n_attn = (size_t)NB * NS * ND;
    const size_t n_w    = (size_t)NB * NH * NS * NS;

    float* attn_dst = nullptr;
    float* w_dst = nullptr;
    if ((size_t)out_size >= n_attn + n_w) { attn_dst = out; w_dst = out + n_attn; }
    else if ((size_t)out_size >= n_w)     { w_dst = out; }
    else                                  { attn_dst = out; }

    float *pq, *pk, *pv, *pa;
    cudaGetSymbolAddress((void**)&pq, g_q);
    cudaGetSymbolAddress((void**)&pk, g_k);
    cudaGetSymbolAddress((void**)&pv, g_v);
    cudaGetSymbolAddress((void**)&pa, g_attn);

    dim3 ggrid(ND / 128, NM / 128);   // (8, 32)
    gemm_tf32<1><<<ggrid, 256>>>(Xq, Wq, bq, pq);
    gemm_tf32<1><<<ggrid, 256>>>(Xk, Wk, bk, pk);
    gemm_tf32<1><<<ggrid, 256>>>(Xv, Wv, bv, pv);

    attn_tf32<<<dim3(NS / 128, NH, NB), 256>>>(msk, w_dst);

    if (w_dst) norm_w<<<NB * NH * NS, 128>>>(w_dst);

    if (attn_dst) gemm_tf32<0><<<ggrid, 256>>>(pa, Wo, bo, attn_dst);
}

// round 6
// speedup vs baseline: 1.2801x; 1.2801x over previous
#include <cuda_runtime.h>
#include <cstdint>

// Problem constants
#define NB 2
#define NS 2048
#define ND 1024
#define NH 16
#define NDH 64
#define NM (NB * NS)

// Scratch (device globals: allocation-free)
__device__ float g_q[(size_t)NB * NH * NS * NDH];
__device__ float g_k[(size_t)NB * NH * NS * NDH];
__device__ float g_v[(size_t)NB * NH * NS * NDH];
__device__ float g_attn[(size_t)NB * NS * ND];
__device__ float g_rowsum[(size_t)NB * NH * NS];

// ---------------- tf32 mma helpers ----------------
__device__ __forceinline__ uint32_t f2tf(float f) {
    uint32_t u;
    asm("cvt.rna.tf32.f32 %0, %1;" : "=r"(u) : "f"(f));
    return u;
}
__device__ __forceinline__ float uaf(uint32_t u) { return __uint_as_float(u); }
__device__ __forceinline__ uint32_t fau(float f) { return __float_as_uint(f); }

__device__ __forceinline__ void mma_tf32(float c[4], const uint32_t a[4], const uint32_t b[2]) {
    asm volatile(
        "mma.sync.aligned.m16n8k8.row.col.f32.tf32.tf32.f32 "
        "{%0,%1,%2,%3}, {%4,%5,%6,%7}, {%8,%9}, {%0,%1,%2,%3};"
        : "+f"(c[0]), "+f"(c[1]), "+f"(c[2]), "+f"(c[3])
        : "r"(a[0]), "r"(a[1]), "r"(a[2]), "r"(a[3]), "r"(b[0]), "r"(b[1]));
}

// ---------------- cp.async helpers ----------------
__device__ __forceinline__ void cpa16(void* smem, const void* g) {
    uint32_t s = (uint32_t)__cvta_generic_to_shared(smem);
    asm volatile("cp.async.cg.shared.global [%0], [%1], 16;" :: "r"(s), "l"(g));
}
__device__ __forceinline__ void cpa_commit() {
    asm volatile("cp.async.commit_group;");
}
__device__ __forceinline__ void cpa_wait0() {
    asm volatile("cp.async.wait_group 0;" ::: "memory");
}
__device__ __forceinline__ void cpa_wait1() {
    asm volatile("cp.async.wait_group 1;" ::: "memory");
}

// ---------------------------------------------------------------------------
// GEMM (round-2 known-good): C = A @ W^T + bias, tf32, single-buffer.
// M=4096, N=K=1024. BM=BN=128, BK=16, 256 threads, warp tile 32x64.
// SPLIT=1: out (b,h,s,dh) PRE-ROUNDED to tf32 (consumed by attn as-is).
// SPLIT=0: row-major (m,n), full f32 (final output).
// ---------------------------------------------------------------------------
#define GS 20
template <int SPLIT>
__global__ __launch_bounds__(256) void gemm_tf32(
    const float* __restrict__ A, const float* __restrict__ W,
    const float* __restrict__ bias, float* __restrict__ out)
{
    __shared__ float As[128 * GS];
    __shared__ float Ws[128 * GS];

    const int tid = threadIdx.x;
    const int wid = tid >> 5, lane = tid & 31;
    const int g = lane >> 2, t = lane & 3;
    const int wm = (wid & 3) * 32;
    const int wn = (wid >> 2) * 64;
    const int bm = blockIdx.y * 128, bn = blockIdx.x * 128;

    const int lr = tid >> 1;
    const int lk = (tid & 1) * 8;

    float c[2][8][4];
#pragma unroll
    for (int i = 0; i < 2; i++)
#pragma unroll
        for (int j = 0; j < 8; j++)
#pragma unroll
            for (int q = 0; q < 4; q++) c[i][j][q] = 0.f;

    const float* aptr = A + (size_t)(bm + lr) * ND + lk;
    const float* wptr = W + (size_t)(bn + lr) * ND + lk;

    for (int k0 = 0; k0 < ND; k0 += 16) {
        float4 a0 = *(const float4*)(aptr + k0);
        float4 a1 = *(const float4*)(aptr + k0 + 4);
        float4 w0 = *(const float4*)(wptr + k0);
        float4 w1 = *(const float4*)(wptr + k0 + 4);
        __syncthreads();
        *(float4*)&As[lr * GS + lk]     = make_float4(uaf(f2tf(a0.x)), uaf(f2tf(a0.y)), uaf(f2tf(a0.z)), uaf(f2tf(a0.w)));
        *(float4*)&As[lr * GS + lk + 4] = make_float4(uaf(f2tf(a1.x)), uaf(f2tf(a1.y)), uaf(f2tf(a1.z)), uaf(f2tf(a1.w)));
        *(float4*)&Ws[lr * GS + lk]     = make_float4(uaf(f2tf(w0.x)), uaf(f2tf(w0.y)), uaf(f2tf(w0.z)), uaf(f2tf(w0.w)));
        *(float4*)&Ws[lr * GS + lk + 4] = make_float4(uaf(f2tf(w1.x)), uaf(f2tf(w1.y)), uaf(f2tf(w1.z)), uaf(f2tf(w1.w)));
        __syncthreads();

#pragma unroll
        for (int kk = 0; kk < 16; kk += 8) {
            uint32_t af[2][4];
#pragma unroll
            for (int mt = 0; mt < 2; mt++) {
                const int r = wm + mt * 16;
                af[mt][0] = fau(As[(r + g)     * GS + kk + t]);
                af[mt][1] = fau(As[(r + g + 8) * GS + kk + t]);
                af[mt][2] = fau(As[(r + g)     * GS + kk + t + 4]);
                af[mt][3] = fau(As[(r + g + 8) * GS + kk + t + 4]);
            }
#pragma unroll
            for (int nt = 0; nt < 8; nt++) {
                uint32_t bf[2];
                const int col = wn + nt * 8;
                bf[0] = fau(Ws[(col + g) * GS + kk + t]);
                bf[1] = fau(Ws[(col + g) * GS + kk + t + 4]);
                mma_tf32(c[0][nt], af[0], bf);
                mma_tf32(c[1][nt], af[1], bf);
            }
        }
    }

#pragma unroll
    for (int mt = 0; mt < 2; mt++) {
#pragma unroll
        for (int rr = 0; rr < 2; rr++) {
            const int m = bm + wm + mt * 16 + g + rr * 8;
            const int b = m >> 11, sIdx = m & (NS - 1);
#pragma unroll
            for (int nt = 0; nt < 8; nt++) {
                const int col = bn + wn + nt * 8 + 2 * t;
                float2 v;
                v.x = c[mt][nt][rr * 2 + 0] + bias[col];
                v.y = c[mt][nt][rr * 2 + 1] + bias[col + 1];
                if (SPLIT) {
                    // Pre-round to tf32: attn consumes these without conversion
                    v.x = uaf(f2tf(v.x));
                    v.y = uaf(f2tf(v.y));
                    const int h = col >> 6, dh = col & 63;
                    *(float2*)&out[((size_t)(b * NH + h) * NS + sIdx) * NDH + dh] = v;
                } else {
                    *(float2*)&out[(size_t)m * ND + col] = v;
                }
            }
        }
    }
}

// ---------------------------------------------------------------------------
// Attention v6 = v2 structure + cp.async double-buffered K/V staging +
// separate E buffer (3 syncs/tile instead of 4) + zero staging conversions
// (q/k/v are pre-rounded tf32).
// Block = 64 q rows, 256 threads (8 warps: 4 m x 2 n). Warp tile 16q x 32k.
// Dynamic smem: Ks 2x64x68, Vs 2x64x72, Es 64x68, red 256 = 90,112 B.
// ---------------------------------------------------------------------------
#define NT_TILES (NS / 64)
__global__ __launch_bounds__(256) void attn_tf32(
    const int* __restrict__ mask, float* __restrict__ wout)
{
    extern __shared__ float dsm[];
    float* KsB = dsm;                        // 2 x 64*68
    float* VsB = dsm + 2 * 64 * 68;          // 2 x 64*72
    float* Es  = VsB + 2 * 64 * 72;          // 64*68
    float* red = Es + 64 * 68;               // 256

    const int b = blockIdx.z, h = blockIdx.y;
    const int q0 = blockIdx.x * 64;
    const int tid = threadIdx.x;
    const int wid = tid >> 5, lane = tid & 31;
    const int g = lane >> 2, t = lane & 3;
    const int wm = (wid & 3) * 16;           // q rows within block
    const int wn = (wid >> 2) * 32;          // key cols (S) / dh cols (PV)
    const size_t bh = (size_t)(b * NH + h);

    // Per-thread staging coordinates (4 chunks of 16B each)
    const int sr = tid >> 4;                 // 0..15 base row
    const int sc = (tid & 15) * 4;           // 0..60 col (floats)

    // Stage Q (pre-converted tf32) into Es via cp.async, build fragments.
    const float* qptr = g_q + (bh * NS + q0) * NDH;
#pragma unroll
    for (int i = 0; i < 4; i++) {
        const int r = sr + i * 16;
        cpa16(&Es[r * 68 + sc], qptr + r * NDH + sc);
    }
    cpa_commit();
    cpa_wait0();
    __syncthreads();

    uint32_t qf[8][4];
#pragma unroll
    for (int kd = 0; kd < 8; kd++) {
        qf[kd][0] = fau(Es[(wm + g)     * 68 + kd * 8 + t]);
        qf[kd][1] = fau(Es[(wm + g + 8) * 68 + kd * 8 + t]);
        qf[kd][2] = fau(Es[(wm + g)     * 68 + kd * 8 + t + 4]);
        qf[kd][3] = fau(Es[(wm + g + 8) * 68 + kd * 8 + t + 4]);
    }
    __syncthreads();   // qf built before Es is reused for E

    float cacc[4][4];
#pragma unroll
    for (int nt = 0; nt < 4; nt++)
#pragma unroll
        for (int q = 0; q < 4; q++) cacc[nt][q] = 0.f;
    float rs0 = 0.f, rs1 = 0.f;

    const int* mbase = mask + (size_t)b * NS * NS;
    float* wbase = wout ? wout + bh * NS * NS : nullptr;
    const float* kbase = g_k + bh * NS * NDH;
    const float* vbase = g_v + bh * NS * NDH;

    // Prologue: issue tile 0 into buffer 0
#pragma unroll
    for (int i = 0; i < 4; i++) {
        const int r = sr + i * 16;
        cpa16(&KsB[r * 68 + sc], kbase + r * NDH + sc);
        cpa16(&VsB[r * 72 + sc], vbase + r * NDH + sc);
    }
    cpa_commit();

    for (int kt = 0; kt < NT_TILES; kt++) {
        // Issue next tile into the other buffer
        if (kt + 1 < NT_TILES) {
            const int nb = (kt + 1) & 1;
            const float* kp = kbase + (size_t)(kt + 1) * 64 * NDH;
            const float* vp = vbase + (size_t)(kt + 1) * 64 * NDH;
            float* kd = KsB + nb * 64 * 68;
            float* vd = VsB + nb * 64 * 72;
#pragma unroll
            for (int i = 0; i < 4; i++) {
                const int r = sr + i * 16;
                cpa16(&kd[r * 68 + sc], kp + r * NDH + sc);
                cpa16(&vd[r * 72 + sc], vp + r * NDH + sc);
            }
            cpa_commit();
            cpa_wait1();   // current tile complete, next in flight
        } else {
            cpa_wait0();
        }
        __syncthreads();   // current tile visible to all warps

        const float* Ks = KsB + (kt & 1) * 64 * 68;
        const float* Vs = VsB + (kt & 1) * 64 * 72;

        // S phase: lg = Q @ K^T for warp's 32-key slice (4 independent chains)
        float lg[4][4];
#pragma unroll
        for (int nt = 0; nt < 4; nt++)
#pragma unroll
            for (int q = 0; q < 4; q++) lg[nt][q] = 0.f;
#pragma unroll
        for (int kk = 0; kk < 8; kk++) {
#pragma unroll
            for (int nt = 0; nt < 4; nt++) {
                const int kc = wn + nt * 8;
                uint32_t bf[2];
                bf[0] = fau(Ks[(kc + g) * 68 + kk * 8 + t]);
                bf[1] = fau(Ks[(kc + g) * 68 + kk * 8 + t + 4]);
                mma_tf32(lg[nt], qf[kk], bf);
            }
        }

        // mask + exp + unnormalized weight write + rowsum; E -> Es (tf32)
        const int qr0 = q0 + wm + g, qr1 = qr0 + 8;
#pragma unroll
        for (int nt = 0; nt < 4; nt++) {
            const int klocal = wn + nt * 8 + 2 * t;
            const int kcg = kt * 64 + klocal;
            int2 m0 = *(const int2*)(mbase + (size_t)qr0 * NS + kcg);
            int2 m1 = *(const int2*)(mbase + (size_t)qr1 * NS + kcg);
            float e0 = m0.x ? 0.f : __expf(lg[nt][0] * 0.125f);
            float e1 = m0.y ? 0.f : __expf(lg[nt][1] * 0.125f);
            float e2 = m1.x ? 0.f : __expf(lg[nt][2] * 0.125f);
            float e3 = m1.y ? 0.f : __expf(lg[nt][3] * 0.125f);
            rs0 += e0 + e1;
            rs1 += e2 + e3;
            if (wbase) {
                *(float2*)&wbase[(size_t)qr0 * NS + kcg] = make_float2(e0, e1);
                *(float2*)&wbase[(size_t)qr1 * NS + kcg] = make_float2(e2, e3);
            }
            *(float2*)&Es[(wm + g)     * 68 + klocal] = make_float2(uaf(f2tf(e0)), uaf(f2tf(e1)));
            *(float2*)&Es[(wm + g + 8) * 68 + klocal] = make_float2(uaf(f2tf(e2)), uaf(f2tf(e3)));
        }
        __syncthreads();   // all E tiles visible

        // PV: cacc += E(64x64) @ V(64x64), warp tile 16q x 32dh
#pragma unroll
        for (int kk = 0; kk < 8; kk++) {
            uint32_t af[4];
            af[0] = fau(Es[(wm + g)     * 68 + kk * 8 + t]);
            af[1] = fau(Es[(wm + g + 8) * 68 + kk * 8 + t]);
            af[2] = fau(Es[(wm + g)     * 68 + kk * 8 + t + 4]);
            af[3] = fau(Es[(wm + g + 8) * 68 + kk * 8 + t + 4]);
#pragma unroll
            for (int nt = 0; nt < 4; nt++) {
                const int dc = wn + nt * 8 + g;
                uint32_t bf[2];
                bf[0] = fau(Vs[(kk * 8 + t)     * 72 + dc]);
                bf[1] = fau(Vs[(kk * 8 + t + 4) * 72 + dc]);
                mma_tf32(cacc[nt], af, bf);
            }
        }
        __syncthreads();   // compute done; next iter may overwrite buffers/Es
    }

    // Rowsums: quad-reduce over t, combine the two n-warps via smem
    rs0 += __shfl_xor_sync(0xffffffffu, rs0, 1);
    rs0 += __shfl_xor_sync(0xffffffffu, rs0, 2);
    rs1 += __shfl_xor_sync(0xffffffffu, rs1, 1);
    rs1 += __shfl_xor_sync(0xffffffffu, rs1, 2);
    if (t == 0) {
        const int half = (wid >= 4) ? 64 : 0;
        red[half + wm + g]     = rs0;
        red[half + wm + g + 8] = rs1;
    }
    __syncthreads();
    const float tot0 = red[wm + g]     + red[64 + wm + g];
    const float tot1 = red[wm + g + 8] + red[64 + wm + g + 8];
    if (wid < 4 && t == 0) {
        g_rowsum[bh * NS + q0 + wm + g]     = tot0;
        g_rowsum[bh * NS + q0 + wm + g + 8] = tot1;
    }
    const float inv0 = 1.f / tot0, inv1 = 1.f / tot1;

    // Normalized attn, concat layout (b, s, h*64 + dh)
    const int q = q0 + wm + g;
#pragma unroll
    for (int nt = 0; nt < 4; nt++) {
        const int dh = wn + nt * 8 + 2 * t;
        *(float2*)&g_attn[((size_t)b * NS + q) * ND + h * NDH + dh] =
            make_float2(cacc[nt][0] * inv0, cacc[nt][1] * inv0);
        *(float2*)&g_attn[((size_t)b * NS + q + 8) * ND + h * NDH + dh] =
            make_float2(cacc[nt][2] * inv1, cacc[nt][3] * inv1);
    }
}

// Scale each weights row by 1/rowsum
__global__ __launch_bounds__(128) void norm_w(float* __restrict__ w)
{
    const int row = blockIdx.x;
    const float inv = 1.f / g_rowsum[row];
    float4* p = (float4*)(w + (size_t)row * NS);
#pragma unroll
    for (int i = threadIdx.x; i < NS / 4; i += 128) {
        float4 v = p[i];
        v.x *= inv; v.y *= inv; v.z *= inv; v.w *= inv;
        p[i] = v;
    }
}

extern "C" void kernel_launch(void* const* d_in, const int* in_sizes, int n_in,
                              void* d_out, int out_size)
{
    const float* Xq  = (const float*)d_in[0];
    const float* Xk  = (const float*)d_in[1];
    const float* Xv  = (const float*)d_in[2];
    const int*   msk = (const int*)d_in[3];
    const float* Wq  = (const float*)d_in[4];
    const float* bq  = (const float*)d_in[5];
    const float* Wk  = (const float*)d_in[6];
    const float* bk  = (const float*)d_in[7];
    const float* Wv  = (const float*)d_in[8];
    const float* bv  = (const float*)d_in[9];
    const float* Wo  = (const float*)d_in[10];
    const float* bo  = (const float*)d_in[11];

    float* out = (float*)d_out;
    const size_t n_attn = (size_t)NB * NS * ND;
    const size_t n_w    = (size_t)NB * NH * NS * NS;

    float* attn_dst = nullptr;
    float* w_dst = nullptr;
    if ((size_t)out_size >= n_attn + n_w) { attn_dst = out; w_dst = out + n_attn; }
    else if ((size_t)out_size >= n_w)     { w_dst = out; }
    else                                  { attn_dst = out; }

    float *pq, *pk, *pv, *pa;
    cudaGetSymbolAddress((void**)&pq, g_q);
    cudaGetSymbolAddress((void**)&pk, g_k);
    cudaGetSymbolAddress((void**)&pv, g_v);
    cudaGetSymbolAddress((void**)&pa, g_attn);

    dim3 ggrid(ND / 128, NM / 128);   // (8, 32)
    gemm_tf32<1><<<ggrid, 256>>>(Xq, Wq, bq, pq);
    gemm_tf32<1><<<ggrid, 256>>>(Xk, Wk, bk, pk);
    gemm_tf32<1><<<ggrid, 256>>>(Xv, Wv, bv, pv);

    const int attn_smem = (2 * 64 * 68 + 2 * 64 * 72 + 64 * 68 + 256) * 4;  // 90,112 B
    cudaFuncSetAttribute(attn_tf32, cudaFuncAttributeMaxDynamicSharedMemorySize, attn_smem);
    attn_tf32<<<dim3(NS / 64, NH, NB), 256, attn_smem>>>(msk, w_dst);

    if (w_dst) norm_w<<<NB * NH * NS, 128>>>(w_dst);

    if (attn_dst) gemm_tf32<0><<<ggrid, 256>>>(pa, Wo, bo, attn_dst);
}

// round 7
// speedup vs baseline: 1.6081x; 1.2562x over previous
#include <cuda_runtime.h>
#include <cuda_fp16.h>
#include <cstdint>

// Problem constants
#define NB 2
#define NS 2048
#define ND 1024
#define NH 16
#define NDH 64
#define NM (NB * NS)

// Scratch (device globals: allocation-free)
__device__ __half g_q[(size_t)NB * NH * NS * NDH];     // [b,h,s,dh]
__device__ __half g_k[(size_t)NB * NH * NS * NDH];     // [b,h,s,dh]
__device__ __half g_v[(size_t)NB * NH * NS * NDH];     // [b,h,dh,s]  TRANSPOSED
__device__ float  g_attn[(size_t)NB * NS * ND];
__device__ float  g_rowsum[(size_t)NB * NH * NS];

// ---------------- helpers ----------------
__device__ __forceinline__ uint32_t f2h2(float a, float b) {
    __half2 h = __floats2half2_rn(a, b);
    return *reinterpret_cast<uint32_t*>(&h);
}

// D(16x8,f32) += A(16x16,f16) * B(16x8,f16)
__device__ __forceinline__ void mma_f16(float c[4], const uint32_t a[4], const uint32_t b[2]) {
    asm volatile(
        "mma.sync.aligned.m16n8k16.row.col.f32.f16.f16.f32 "
        "{%0,%1,%2,%3}, {%4,%5,%6,%7}, {%8,%9}, {%0,%1,%2,%3};"
        : "+f"(c[0]), "+f"(c[1]), "+f"(c[2]), "+f"(c[3])
        : "r"(a[0]), "r"(a[1]), "r"(a[2]), "r"(a[3]), "r"(b[0]), "r"(b[1]));
}

__device__ __forceinline__ void cpa16(void* smem, const void* g) {
    uint32_t s = (uint32_t)__cvta_generic_to_shared(smem);
    asm volatile("cp.async.cg.shared.global [%0], [%1], 16;" :: "r"(s), "l"(g));
}
__device__ __forceinline__ void cpa_commit() { asm volatile("cp.async.commit_group;"); }
__device__ __forceinline__ void cpa_wait0() { asm volatile("cp.async.wait_group 0;" ::: "memory"); }
__device__ __forceinline__ void cpa_wait1() { asm volatile("cp.async.wait_group 1;" ::: "memory"); }

// ---------------------------------------------------------------------------
// GEMM: C = A(f32, MxK) @ W^T(f32, NxK) + bias, fp16 tensor cores, f32 accum.
// M=4096, N=K=1024. BM=BN=128, BK=32, 256 threads, warp tile 32x64.
// MODE 0: f32 row-major out. MODE 1: half out [b,h,s,dh]. MODE 2: half out
// [b,h,dh,s] (transposed, for V).
// smem rows stride 20 uint32 (16 half2 pairs + 4 pad): fragment reads use
// banks {20g+t mod 32} = all distinct -> conflict-free.
// ---------------------------------------------------------------------------
template <int MODE>
__global__ __launch_bounds__(256) void gemm_f16(
    const float* __restrict__ A, const float* __restrict__ W,
    const float* __restrict__ bias, void* __restrict__ outv)
{
    __shared__ uint32_t As[128 * 20];
    __shared__ uint32_t Ws[128 * 20];

    const int tid = threadIdx.x;
    const int wid = tid >> 5, lane = tid & 31;
    const int g = lane >> 2, t = lane & 3;
    const int wm = (wid & 3) * 32;
    const int wn = (wid >> 2) * 64;
    const int bm = blockIdx.y * 128, bn = blockIdx.x * 128;

    const int lr = tid >> 1;            // staging row 0..127
    const int lp = (tid & 1) * 8;       // pair offset 0/8 (16 halves per thread)

    float c[2][8][4];
#pragma unroll
    for (int i = 0; i < 2; i++)
#pragma unroll
        for (int j = 0; j < 8; j++)
#pragma unroll
            for (int q = 0; q < 4; q++) c[i][j][q] = 0.f;

    const float* aptr = A + (size_t)(bm + lr) * ND + lp * 2;
    const float* wptr = W + (size_t)(bn + lr) * ND + lp * 2;

    for (int k0 = 0; k0 < ND; k0 += 32) {
        float4 a0 = *(const float4*)(aptr + k0);
        float4 a1 = *(const float4*)(aptr + k0 + 4);
        float4 a2 = *(const float4*)(aptr + k0 + 8);
        float4 a3 = *(const float4*)(aptr + k0 + 12);
        float4 w0 = *(const float4*)(wptr + k0);
        float4 w1 = *(const float4*)(wptr + k0 + 4);
        float4 w2 = *(const float4*)(wptr + k0 + 8);
        float4 w3 = *(const float4*)(wptr + k0 + 12);
        __syncthreads();
        *(uint4*)&As[lr * 20 + lp] =
            make_uint4(f2h2(a0.x, a0.y), f2h2(a0.z, a0.w), f2h2(a1.x, a1.y), f2h2(a1.z, a1.w));
        *(uint4*)&As[lr * 20 + lp + 4] =
            make_uint4(f2h2(a2.x, a2.y), f2h2(a2.z, a2.w), f2h2(a3.x, a3.y), f2h2(a3.z, a3.w));
        *(uint4*)&Ws[lr * 20 + lp] =
            make_uint4(f2h2(w0.x, w0.y), f2h2(w0.z, w0.w), f2h2(w1.x, w1.y), f2h2(w1.z, w1.w));
        *(uint4*)&Ws[lr * 20 + lp + 4] =
            make_uint4(f2h2(w2.x, w2.y), f2h2(w2.z, w2.w), f2h2(w3.x, w3.y), f2h2(w3.z, w3.w));
        __syncthreads();

#pragma unroll
        for (int ch = 0; ch < 2; ch++) {     // two k16 chunks per BK=32
            uint32_t af[2][4];
#pragma unroll
            for (int mt = 0; mt < 2; mt++) {
                const int r = wm + mt * 16;
                af[mt][0] = As[(r + g)     * 20 + ch * 8 + t];
                af[mt][1] = As[(r + g + 8) * 20 + ch * 8 + t];
                af[mt][2] = As[(r + g)     * 20 + ch * 8 + t + 4];
                af[mt][3] = As[(r + g + 8) * 20 + ch * 8 + t + 4];
            }
#pragma unroll
            for (int nt = 0; nt < 8; nt++) {
                uint32_t bf[2];
                const int col = wn + nt * 8;
                bf[0] = Ws[(col + g) * 20 + ch * 8 + t];
                bf[1] = Ws[(col + g) * 20 + ch * 8 + t + 4];
                mma_f16(c[0][nt], af[0], bf);
                mma_f16(c[1][nt], af[1], bf);
            }
        }
    }

#pragma unroll
    for (int mt = 0; mt < 2; mt++) {
#pragma unroll
        for (int rr = 0; rr < 2; rr++) {
            const int m = bm + wm + mt * 16 + g + rr * 8;
            const int b = m >> 11, sIdx = m & (NS - 1);
#pragma unroll
            for (int nt = 0; nt < 8; nt++) {
                const int col = bn + wn + nt * 8 + 2 * t;
                const float vx = c[mt][nt][rr * 2 + 0] + bias[col];
                const float vy = c[mt][nt][rr * 2 + 1] + bias[col + 1];
                if (MODE == 0) {
                    *(float2*)&((float*)outv)[(size_t)m * ND + col] = make_float2(vx, vy);
                } else if (MODE == 1) {
                    const int h = col >> 6, dh = col & 63;
                    *(uint32_t*)&((__half*)outv)[((size_t)(b * NH + h) * NS + sIdx) * NDH + dh] =
                        f2h2(vx, vy);
                } else {
                    const int h = col >> 6, dh = col & 63;
                    __half* o = (__half*)outv + ((size_t)(b * NH + h) * NDH) * NS;
                    o[(size_t)dh * NS + sIdx]       = __float2half_rn(vx);
                    o[(size_t)(dh + 1) * NS + sIdx] = __float2half_rn(vy);
                }
            }
        }
    }
}

// ---------------------------------------------------------------------------
// Attention v7 (fp16): v6 structure, m16n8k16.
// Block = 64 q rows, 256 threads (8 warps: 4m x 2n). Warp tile 16q x 32k.
// K tiles [key][32 pairs], V tiles TRANSPOSED [dh][32 key-pairs] (producer
// wrote g_v as [b,h,dh,s]). Row stride 36 uint32 -> frag banks {4g+t}
// conflict-free. cp.async double-buffered K/V; separate E buffer; 3 syncs.
// Dynamic smem: (2+2+1) * 64*36 uint32 + red = ~46.7 KB.
// ---------------------------------------------------------------------------
#define NT_TILES (NS / 64)
#define KST 36
__global__ __launch_bounds__(256) void attn_f16(
    const int* __restrict__ mask, float* __restrict__ wout)
{
    extern __shared__ uint32_t dsm[];
    uint32_t* KsB = dsm;                       // 2 x 64*36
    uint32_t* VsB = dsm + 2 * 64 * KST;        // 2 x 64*36
    uint32_t* Es  = VsB + 2 * 64 * KST;        // 64*36
    float*    red = (float*)(Es + 64 * KST);   // 128 floats

    const int b = blockIdx.z, h = blockIdx.y;
    const int q0 = blockIdx.x * 64;
    const int tid = threadIdx.x;
    const int wid = tid >> 5, lane = tid & 31;
    const int g = lane >> 2, t = lane & 3;
    const int wm = (wid & 3) * 16;             // q rows within block
    const int wn = (wid >> 2) * 32;            // key cols (S) / dh cols (PV)
    const size_t bh = (size_t)(b * NH + h);

    // Staging coords: 64 rows x 8 chunks(16B); thread does chunks c and c+4
    const int sr = tid >> 2;                   // row 0..63
    const int sch = tid & 3;                   // chunk 0..3

    // Stage Q (half, 64x64) into Es
    const __half* qptr = g_q + (bh * NS + q0) * NDH;
    cpa16(&Es[sr * KST + sch * 4],      qptr + sr * NDH + sch * 8);
    cpa16(&Es[sr * KST + sch * 4 + 16], qptr + sr * NDH + sch * 8 + 32);
    cpa_commit();
    cpa_wait0();
    __syncthreads();

    // Q fragments: 4 k16-chunks x 4 regs = 16 registers
    uint32_t qf[4][4];
#pragma unroll
    for (int ch = 0; ch < 4; ch++) {
        qf[ch][0] = Es[(wm + g)     * KST + ch * 8 + t];
        qf[ch][1] = Es[(wm + g + 8) * KST + ch * 8 + t];
        qf[ch][2] = Es[(wm + g)     * KST + ch * 8 + t + 4];
        qf[ch][3] = Es[(wm + g + 8) * KST + ch * 8 + t + 4];
    }
    __syncthreads();   // qf built before Es is reused for E

    float cacc[4][4];
#pragma unroll
    for (int nt = 0; nt < 4; nt++)
#pragma unroll
        for (int q = 0; q < 4; q++) cacc[nt][q] = 0.f;
    float rs0 = 0.f, rs1 = 0.f;

    const int* mbase = mask + (size_t)b * NS * NS;
    float* wbase = wout ? wout + bh * NS * NS : nullptr;
    const __half* kbase = g_k + bh * NS * NDH;         // [s][dh]
    const __half* vbase = g_v + bh * (size_t)NDH * NS; // [dh][s]

    // Prologue: tile 0 into buffer 0. K rows = keys; V rows = dh.
    cpa16(&KsB[sr * KST + sch * 4],      kbase + sr * NDH + sch * 8);
    cpa16(&KsB[sr * KST + sch * 4 + 16], kbase + sr * NDH + sch * 8 + 32);
    cpa16(&VsB[sr * KST + sch * 4],      vbase + (size_t)sr * NS + sch * 8);
    cpa16(&VsB[sr * KST + sch * 4 + 16], vbase + (size_t)sr * NS + sch * 8 + 32);
    cpa_commit();

    for (int kt = 0; kt < NT_TILES; kt++) {
        if (kt + 1 < NT_TILES) {
            const int nb = (kt + 1) & 1;
            const __half* kp = kbase + (size_t)(kt + 1) * 64 * NDH;
            const __half* vp = vbase + (size_t)(kt + 1) * 64;   // col offset in [dh][s]
            uint32_t* kd = KsB + nb * 64 * KST;
            uint32_t* vd = VsB + nb * 64 * KST;
            cpa16(&kd[sr * KST + sch * 4],      kp + sr * NDH + sch * 8);
            cpa16(&kd[sr * KST + sch * 4 + 16], kp + sr * NDH + sch * 8 + 32);
            cpa16(&vd[sr * KST + sch * 4],      vp + (size_t)sr * NS + sch * 8);
            cpa16(&vd[sr * KST + sch * 4 + 16], vp + (size_t)sr * NS + sch * 8 + 32);
            cpa_commit();
            cpa_wait1();
        } else {
            cpa_wait0();
        }
        __syncthreads();

        const uint32_t* Ks = KsB + (kt & 1) * 64 * KST;
        const uint32_t* Vs = VsB + (kt & 1) * 64 * KST;

        // S phase: lg = Q @ K^T for warp's 32-key slice
        float lg[4][4];
#pragma unroll
        for (int nt = 0; nt < 4; nt++)
#pragma unroll
            for (int q = 0; q < 4; q++) lg[nt][q] = 0.f;
#pragma unroll
        for (int ch = 0; ch < 4; ch++) {
#pragma unroll
            for (int nt = 0; nt < 4; nt++) {
                const int kc = wn + nt * 8;
                uint32_t bf[2];
                bf[0] = Ks[(kc + g) * KST + ch * 8 + t];
                bf[1] = Ks[(kc + g) * KST + ch * 8 + t + 4];
                mma_f16(lg[nt], qf[ch], bf);
            }
        }

        // mask + exp + unnormalized weight write + rowsum; E -> Es (half2)
        const int qr0 = q0 + wm + g, qr1 = qr0 + 8;
#pragma unroll
        for (int nt = 0; nt < 4; nt++) {
            const int klocal = wn + nt * 8 + 2 * t;
            const int kcg = kt * 64 + klocal;
            int2 m0 = *(const int2*)(mbase + (size_t)qr0 * NS + kcg);
            int2 m1 = *(const int2*)(mbase + (size_t)qr1 * NS + kcg);
            float e0 = m0.x ? 0.f : __expf(lg[nt][0] * 0.125f);
            float e1 = m0.y ? 0.f : __expf(lg[nt][1] * 0.125f);
            float e2 = m1.x ? 0.f : __expf(lg[nt][2] * 0.125f);
            float e3 = m1.y ? 0.f : __expf(lg[nt][3] * 0.125f);
            rs0 += e0 + e1;
            rs1 += e2 + e3;
            if (wbase) {
                *(float2*)&wbase[(size_t)qr0 * NS + kcg] = make_float2(e0, e1);
                *(float2*)&wbase[(size_t)qr1 * NS + kcg] = make_float2(e2, e3);
            }
            const int pair = (klocal >> 1);                  // wn/2 + nt*4 + t
            Es[(wm + g)     * KST + pair] = f2h2(e0, e1);
            Es[(wm + g + 8) * KST + pair] = f2h2(e2, e3);
        }
        __syncthreads();   // all E tiles visible

        // PV: cacc += E(64x64) @ V^T-tile; V is [dh][key-pairs] (K-major)
#pragma unroll
        for (int ch = 0; ch < 4; ch++) {
            uint32_t af[4];
            af[0] = Es[(wm + g)     * KST + ch * 8 + t];
            af[1] = Es[(wm + g + 8) * KST + ch * 8 + t];
            af[2] = Es[(wm + g)     * KST + ch * 8 + t + 4];
            af[3] = Es[(wm + g + 8) * KST + ch * 8 + t + 4];
#pragma unroll
            for (int nt = 0; nt < 4; nt++) {
                const int dc = wn + nt * 8 + g;              // dh column
                uint32_t bf[2];
                bf[0] = Vs[dc * KST + ch * 8 + t];
                bf[1] = Vs[dc * KST + ch * 8 + t + 4];
                mma_f16(cacc[nt], af, bf);
            }
        }
        __syncthreads();   // compute done before buffers/Es overwritten
    }

    // Rowsums: quad-reduce over t, combine the two n-warps via smem
    rs0 += __shfl_xor_sync(0xffffffffu, rs0, 1);
    rs0 += __shfl_xor_sync(0xffffffffu, rs0, 2);
    rs1 += __shfl_xor_sync(0xffffffffu, rs1, 1);
    rs1 += __shfl_xor_sync(0xffffffffu, rs1, 2);
    if (t == 0) {
        const int half = (wid >= 4) ? 64 : 0;
        red[half + wm + g]     = rs0;
        red[half + wm + g + 8] = rs1;
    }
    __syncthreads();
    const float tot0 = red[wm + g]     + red[64 + wm + g];
    const float tot1 = red[wm + g + 8] + red[64 + wm + g + 8];
    if (wid < 4 && t == 0) {
        g_rowsum[bh * NS + q0 + wm + g]     = tot0;
        g_rowsum[bh * NS + q0 + wm + g + 8] = tot1;
    }
    const float inv0 = 1.f / tot0, inv1 = 1.f / tot1;

    // Normalized attn, concat layout (b, s, h*64 + dh), f32
    const int q = q0 + wm + g;
#pragma unroll
    for (int nt = 0; nt < 4; nt++) {
        const int dh = wn + nt * 8 + 2 * t;
        *(float2*)&g_attn[((size_t)b * NS + q) * ND + h * NDH + dh] =
            make_float2(cacc[nt][0] * inv0, cacc[nt][1] * inv0);
        *(float2*)&g_attn[((size_t)b * NS + q + 8) * ND + h * NDH + dh] =
            make_float2(cacc[nt][2] * inv1, cacc[nt][3] * inv1);
    }
}

// Scale each weights row by 1/rowsum
__global__ __launch_bounds__(128) void norm_w(float* __restrict__ w)
{
    const int row = blockIdx.x;
    const float inv = 1.f / g_rowsum[row];
    float4* p = (float4*)(w + (size_t)row * NS);
#pragma unroll
    for (int i = threadIdx.x; i < NS / 4; i += 128) {
        float4 v = p[i];
        v.x *= inv; v.y *= inv; v.z *= inv; v.w *= inv;
        p[i] = v;
    }
}

extern "C" void kernel_launch(void* const* d_in, const int* in_sizes, int n_in,
                              void* d_out, int out_size)
{
    const float* Xq  = (const float*)d_in[0];
    const float* Xk  = (const float*)d_in[1];
    const float* Xv  = (const float*)d_in[2];
    const int*   msk = (const int*)d_in[3];
    const float* Wq  = (const float*)d_in[4];
    const float* bq  = (const float*)d_in[5];
    const float* Wk  = (const float*)d_in[6];
    const float* bk  = (const float*)d_in[7];
    const float* Wv  = (const float*)d_in[8];
    const float* bv  = (const float*)d_in[9];
    const float* Wo  = (const float*)d_in[10];
    const float* bo  = (const float*)d_in[11];

    float* out = (float*)d_out;
    const size_t n_attn = (size_t)NB * NS * ND;
    const size_t n_w    = (size_t)NB * NH * NS * NS;

    float* attn_dst = nullptr;
    float* w_dst = nullptr;
    if ((size_t)out_size >= n_attn + n_w) { attn_dst = out; w_dst = out + n_attn; }
    else if ((size_t)out_size >= n_w)     { w_dst = out; }
    else                                  { attn_dst = out; }

    __half *pq, *pk, *pv;
    float *pa;
    cudaGetSymbolAddress((void**)&pq, g_q);
    cudaGetSymbolAddress((void**)&pk, g_k);
    cudaGetSymbolAddress((void**)&pv, g_v);
    cudaGetSymbolAddress((void**)&pa, g_attn);

    dim3 ggrid(ND / 128, NM / 128);   // (8, 32)
    gemm_f16<1><<<ggrid, 256>>>(Xq, Wq, bq, pq);
    gemm_f16<1><<<ggrid, 256>>>(Xk, Wk, bk, pk);
    gemm_f16<2><<<ggrid, 256>>>(Xv, Wv, bv, pv);   // V transposed [b,h,dh,s]

    const int attn_smem = (5 * 64 * KST) * 4 + 128 * 4 + 256;  // ~46.8 KB
    cudaFuncSetAttribute(attn_f16, cudaFuncAttributeMaxDynamicSharedMemorySize, attn_smem);
    attn_f16<<<dim3(NS / 64, NH, NB), 256, attn_smem>>>(msk, w_dst);

    if (w_dst) norm_w<<<NB * NH * NS, 128>>>(w_dst);

    if (attn_dst) gemm_f16<0><<<ggrid, 256>>>(pa, Wo, bo, attn_dst);
}